// round 8
// baseline (speedup 1.0000x reference)
#include <cuda_runtime.h>
#include <cuda_bf16.h>

#define N_NODES 100000
#define N_EDGES 6400000

// ---------------- scratch: all scalar SoA, allocation-free __device__ globals ----
__device__ int   g_deg [N_NODES];
__device__ float g_dinv[N_NODES];
// pre-scaled per-node features (width up to 4)
__device__ float g_h0[N_NODES];
__device__ float g_h1[N_NODES];
__device__ float g_h2[N_NODES];
__device__ float g_h3[N_NODES];
// scatter accumulators
__device__ float g_a0[N_NODES];
__device__ float g_a1[N_NODES];
__device__ float g_a2[N_NODES];
__device__ float g_a3[N_NODES];
// validated (clamped) edge lists
__device__ int   g_src[N_EDGES];
__device__ int   g_dst[N_EDGES];

// ---------------- degree / prep ----------------
__global__ void k_deg_init() {
    int n = blockIdx.x * blockDim.x + threadIdx.x;
    if (n < N_NODES) g_deg[n] = 1;               // self-loop
}

// edge_index is int32 on device: [2, E] row-major -> src = ei[0..E), dst = ei[E..2E)
__global__ void k_prep(const int* __restrict__ src,
                       const int* __restrict__ dst) {
    int e = blockIdx.x * blockDim.x + threadIdx.x;
    if (e >= N_EDGES) return;
    int s = src[e];
    int d = dst[e];
    // defensive clamp: if dtype/layout assumption is wrong we get a finite
    // rel_err diagnostic instead of an address-space trap.
    s = min(max(s, 0), N_NODES - 1);
    d = min(max(d, 0), N_NODES - 1);
    g_src[e] = s;
    g_dst[e] = d;
    atomicAdd(&g_deg[d], 1);
}

__global__ void k_dinv() {
    int n = blockIdx.x * blockDim.x + threadIdx.x;
    if (n < N_NODES) g_dinv[n] = rsqrtf((float)g_deg[n]);
}

// ---------------- layer 1: h = (x @ W1) * dinv ; acc = h (self-loop) ----------------
// warp-per-node: 128 features, 4 per lane, coalesced row reads.
__global__ void k_mm1(const float* __restrict__ x, const float* __restrict__ W1) {
    __shared__ float sW[512];                     // W1 is 128x4 row-major
    for (int i = threadIdx.x; i < 512; i += blockDim.x) sW[i] = W1[i];
    __syncthreads();

    int warp = threadIdx.x >> 5;
    int lane = threadIdx.x & 31;
    int n = blockIdx.x * (blockDim.x >> 5) + warp;
    if (n >= N_NODES) return;

    const float* xr = x + (size_t)n * 128;
    float p0 = 0.f, p1 = 0.f, p2 = 0.f, p3 = 0.f;
#pragma unroll
    for (int i = 0; i < 4; i++) {
        int k = lane + 32 * i;
        float xv = xr[k];
        p0 += xv * sW[k * 4 + 0];
        p1 += xv * sW[k * 4 + 1];
        p2 += xv * sW[k * 4 + 2];
        p3 += xv * sW[k * 4 + 3];
    }
#pragma unroll
    for (int off = 16; off > 0; off >>= 1) {
        p0 += __shfl_down_sync(0xFFFFFFFFu, p0, off);
        p1 += __shfl_down_sync(0xFFFFFFFFu, p1, off);
        p2 += __shfl_down_sync(0xFFFFFFFFu, p2, off);
        p3 += __shfl_down_sync(0xFFFFFFFFu, p3, off);
    }
    if (lane == 0) {
        float di = g_dinv[n];
        float v0 = p0 * di, v1 = p1 * di, v2 = p2 * di, v3 = p3 * di;
        g_h0[n] = v0; g_h1[n] = v1; g_h2[n] = v2; g_h3[n] = v3;
        g_a0[n] = v0; g_a1[n] = v1; g_a2[n] = v2; g_a3[n] = v3;  // self-loop
    }
}

// ---------------- edge scatter, width 4 (scalar atomics into distinct arrays) ----
__global__ void k_edge4() {
    int e = blockIdx.x * blockDim.x + threadIdx.x;
    if (e >= N_EDGES) return;
    int s = g_src[e];
    int d = g_dst[e];
    atomicAdd(&g_a0[d], g_h0[s]);
    atomicAdd(&g_a1[d], g_h1[s]);
    atomicAdd(&g_a2[d], g_h2[s]);
    atomicAdd(&g_a3[d], g_h3[s]);
}

// ---------------- finalize L1 + matmul L2 (4x4) ----------------
__global__ void k_f1mm2(const float* __restrict__ b1, const float* __restrict__ W2) {
    int n = blockIdx.x * blockDim.x + threadIdx.x;
    if (n >= N_NODES) return;
    float di = g_dinv[n];
    float h0 = tanhf(di * g_a0[n] + b1[0]);
    float h1 = tanhf(di * g_a1[n] + b1[1]);
    float h2 = tanhf(di * g_a2[n] + b1[2]);
    float h3 = tanhf(di * g_a3[n] + b1[3]);
    float v0 = (h0 * W2[0] + h1 * W2[4] + h2 * W2[8]  + h3 * W2[12]) * di;
    float v1 = (h0 * W2[1] + h1 * W2[5] + h2 * W2[9]  + h3 * W2[13]) * di;
    float v2 = (h0 * W2[2] + h1 * W2[6] + h2 * W2[10] + h3 * W2[14]) * di;
    float v3 = (h0 * W2[3] + h1 * W2[7] + h2 * W2[11] + h3 * W2[15]) * di;
    g_h0[n] = v0; g_h1[n] = v1; g_h2[n] = v2; g_h3[n] = v3;
    g_a0[n] = v0; g_a1[n] = v1; g_a2[n] = v2; g_a3[n] = v3;      // self-loop
}

// ---------------- finalize L2 + matmul L3 (4x2) ----------------
__global__ void k_f2mm3(const float* __restrict__ b2, const float* __restrict__ W3) {
    int n = blockIdx.x * blockDim.x + threadIdx.x;
    if (n >= N_NODES) return;
    float di = g_dinv[n];
    float h0 = tanhf(di * g_a0[n] + b2[0]);
    float h1 = tanhf(di * g_a1[n] + b2[1]);
    float h2 = tanhf(di * g_a2[n] + b2[2]);
    float h3 = tanhf(di * g_a3[n] + b2[3]);
    float v0 = (h0 * W3[0] + h1 * W3[2] + h2 * W3[4] + h3 * W3[6]) * di;
    float v1 = (h0 * W3[1] + h1 * W3[3] + h2 * W3[5] + h3 * W3[7]) * di;
    g_h0[n] = v0; g_h1[n] = v1;
    g_a0[n] = v0; g_a1[n] = v1;                                  // self-loop
}

// ---------------- edge scatter, width 2 ----------------
__global__ void k_edge2() {
    int e = blockIdx.x * blockDim.x + threadIdx.x;
    if (e >= N_EDGES) return;
    int s = g_src[e];
    int d = g_dst[e];
    atomicAdd(&g_a0[d], g_h0[s]);
    atomicAdd(&g_a1[d], g_h1[s]);
}

// ---------------- finalize L3 + classifier ----------------
__global__ void k_final(const float* __restrict__ b3,
                        const float* __restrict__ Wc, const float* __restrict__ bc,
                        float* __restrict__ out, float* __restrict__ hout) {
    int n = blockIdx.x * blockDim.x + threadIdx.x;
    if (n >= N_NODES) return;
    float di = g_dinv[n];
    float h0 = tanhf(di * g_a0[n] + b3[0]);
    float h1 = tanhf(di * g_a1[n] + b3[1]);
    float* o = out + (size_t)n * 10;
#pragma unroll
    for (int j = 0; j < 10; j++)
        o[j] = h0 * Wc[j] + h1 * Wc[10 + j] + bc[j];
    hout[2 * n + 0] = h0;
    hout[2 * n + 1] = h1;
}

// ---------------- launch ----------------
extern "C" void kernel_launch(void* const* d_in, const int* in_sizes, int n_in,
                              void* d_out, int out_size) {
    const float* x  = (const float*)d_in[0];
    const int*   ei = (const int*)d_in[1];        // int32 on device, [2, E] row-major
    const float* W1 = (const float*)d_in[2];
    const float* b1 = (const float*)d_in[3];
    const float* W2 = (const float*)d_in[4];
    const float* b2 = (const float*)d_in[5];
    const float* W3 = (const float*)d_in[6];
    const float* b3 = (const float*)d_in[7];
    const float* Wc = (const float*)d_in[8];
    const float* bc = (const float*)d_in[9];

    const int* src = ei;            // row 0
    const int* dst = ei + N_EDGES;  // row 1

    float* out  = (float*)d_out;                  // [N, 10]
    float* hout = out + (size_t)N_NODES * 10;     // [N, 2]

    const int T = 256;
    const int nodeBlocks = (N_NODES + T - 1) / T;
    const int edgeBlocks = (N_EDGES + T - 1) / T;
    const int mm1Blocks  = (N_NODES + 7) / 8;     // 8 warps/block, warp-per-node

    k_deg_init <<<nodeBlocks, T>>>();
    k_prep     <<<edgeBlocks, T>>>(src, dst);
    k_dinv     <<<nodeBlocks, T>>>();

    k_mm1      <<<mm1Blocks, T>>>(x, W1);
    k_edge4    <<<edgeBlocks, T>>>();

    k_f1mm2    <<<nodeBlocks, T>>>(b1, W2);
    k_edge4    <<<edgeBlocks, T>>>();

    k_f2mm3    <<<nodeBlocks, T>>>(b2, W3);
    k_edge2    <<<edgeBlocks, T>>>();

    k_final    <<<nodeBlocks, T>>>(b3, Wc, bc, out, hout);
}

// round 9
// speedup vs baseline: 2.2143x; 2.2143x over previous
#include <cuda_runtime.h>
#include <cuda_bf16.h>

#define N_NODES 100000
#define N_EDGES 6400000

// ---------------- scratch (allocation-free __device__ globals) ----------------
__device__ int    g_deg [N_NODES];
__device__ float  g_dinv[N_NODES];
__device__ float4 g_f4  [N_NODES];   // pre-scaled per-node features (width 4)
__device__ float4 g_c4  [N_NODES];   // scatter accumulator (width 4)
__device__ float2 g_f2  [N_NODES];   // width-2 (layer 3)
__device__ float2 g_c2  [N_NODES];
__device__ int2   g_e   [N_EDGES];   // validated (src, dst) pairs

// ---------------- vector reductions (sm_90+; addresses validated in k_prep) ----
__device__ __forceinline__ void red_add_v4(float4* addr, float4 v) {
    asm volatile("red.global.add.v4.f32 [%0], {%1,%2,%3,%4};"
                 :: "l"(addr), "f"(v.x), "f"(v.y), "f"(v.z), "f"(v.w) : "memory");
}
__device__ __forceinline__ void red_add_v2(float2* addr, float2 v) {
    asm volatile("red.global.add.v2.f32 [%0], {%1,%2};"
                 :: "l"(addr), "f"(v.x), "f"(v.y) : "memory");
}

// ---------------- degree / prep ----------------
__global__ void k_deg_init() {
    int n = blockIdx.x * blockDim.x + threadIdx.x;
    if (n < N_NODES) g_deg[n] = 1;               // self-loop
}

// edge_index is int32 on device: [2, E] row-major
__global__ void k_prep(const int* __restrict__ src,
                       const int* __restrict__ dst) {
    int e = blockIdx.x * blockDim.x + threadIdx.x;
    if (e >= N_EDGES) return;
    int s = src[e];
    int d = dst[e];
    s = min(max(s, 0), N_NODES - 1);             // keep RED addresses provably in-bounds
    d = min(max(d, 0), N_NODES - 1);
    g_e[e] = make_int2(s, d);
    atomicAdd(&g_deg[d], 1);
}

__global__ void k_dinv() {
    int n = blockIdx.x * blockDim.x + threadIdx.x;
    if (n < N_NODES) g_dinv[n] = rsqrtf((float)g_deg[n]);
}

// ---------------- layer 1: f = (x @ W1) * dinv ; acc = f (self-loop) ----------------
// warp-per-node; each lane loads one float4 (whole 512B row per warp).
__global__ void k_mm1(const float* __restrict__ x, const float* __restrict__ W1) {
    __shared__ float4 sW[128];                   // W1 rows (128x4) as float4
    const float4* W4 = (const float4*)W1;
    for (int i = threadIdx.x; i < 128; i += blockDim.x) sW[i] = W4[i];
    __syncthreads();

    int warp = threadIdx.x >> 5;
    int lane = threadIdx.x & 31;
    int n = blockIdx.x * (blockDim.x >> 5) + warp;
    if (n >= N_NODES) return;

    const float4* xr4 = (const float4*)(x + (size_t)n * 128);
    float4 xv = xr4[lane];                       // cols 4*lane .. 4*lane+3
    float p0 = 0.f, p1 = 0.f, p2 = 0.f, p3 = 0.f;
    const float* xs = (const float*)&xv;
#pragma unroll
    for (int i = 0; i < 4; i++) {
        int k = 4 * lane + i;
        float xi = xs[i];
        float4 w = sW[k];
        p0 += xi * w.x; p1 += xi * w.y; p2 += xi * w.z; p3 += xi * w.w;
    }
#pragma unroll
    for (int off = 16; off > 0; off >>= 1) {
        p0 += __shfl_down_sync(0xFFFFFFFFu, p0, off);
        p1 += __shfl_down_sync(0xFFFFFFFFu, p1, off);
        p2 += __shfl_down_sync(0xFFFFFFFFu, p2, off);
        p3 += __shfl_down_sync(0xFFFFFFFFu, p3, off);
    }
    if (lane == 0) {
        float di = g_dinv[n];
        float4 g = make_float4(p0 * di, p1 * di, p2 * di, p3 * di);
        g_f4[n] = g;
        g_c4[n] = g;                             // self-loop contribution
    }
}

// ---------------- edge scatter, width 4: 1 gather sector + 1 RED sector ----------
__global__ void k_edge4() {
    int e = blockIdx.x * blockDim.x + threadIdx.x;
    if (e >= N_EDGES) return;
    int2 sd = g_e[e];
    float4 v = g_f4[sd.x];
    red_add_v4(&g_c4[sd.y], v);
}

// ---------------- finalize L1 + matmul L2 (4x4) ----------------
__global__ void k_f1mm2(const float* __restrict__ b1, const float* __restrict__ W2) {
    int n = blockIdx.x * blockDim.x + threadIdx.x;
    if (n >= N_NODES) return;
    float di = g_dinv[n];
    float4 a = g_c4[n];
    float h0 = tanhf(di * a.x + b1[0]);
    float h1 = tanhf(di * a.y + b1[1]);
    float h2 = tanhf(di * a.z + b1[2]);
    float h3 = tanhf(di * a.w + b1[3]);
    float4 g;
    g.x = (h0 * W2[0] + h1 * W2[4] + h2 * W2[8]  + h3 * W2[12]) * di;
    g.y = (h0 * W2[1] + h1 * W2[5] + h2 * W2[9]  + h3 * W2[13]) * di;
    g.z = (h0 * W2[2] + h1 * W2[6] + h2 * W2[10] + h3 * W2[14]) * di;
    g.w = (h0 * W2[3] + h1 * W2[7] + h2 * W2[11] + h3 * W2[15]) * di;
    g_f4[n] = g;
    g_c4[n] = g;                                 // self-loop
}

// ---------------- finalize L2 + matmul L3 (4x2) ----------------
__global__ void k_f2mm3(const float* __restrict__ b2, const float* __restrict__ W3) {
    int n = blockIdx.x * blockDim.x + threadIdx.x;
    if (n >= N_NODES) return;
    float di = g_dinv[n];
    float4 a = g_c4[n];
    float h0 = tanhf(di * a.x + b2[0]);
    float h1 = tanhf(di * a.y + b2[1]);
    float h2 = tanhf(di * a.z + b2[2]);
    float h3 = tanhf(di * a.w + b2[3]);
    float2 g;
    g.x = (h0 * W3[0] + h1 * W3[2] + h2 * W3[4] + h3 * W3[6]) * di;
    g.y = (h0 * W3[1] + h1 * W3[3] + h2 * W3[5] + h3 * W3[7]) * di;
    g_f2[n] = g;
    g_c2[n] = g;                                 // self-loop
}

// ---------------- edge scatter, width 2 ----------------
__global__ void k_edge2() {
    int e = blockIdx.x * blockDim.x + threadIdx.x;
    if (e >= N_EDGES) return;
    int2 sd = g_e[e];
    float2 v = g_f2[sd.x];
    red_add_v2(&g_c2[sd.y], v);
}

// ---------------- finalize L3 + classifier ----------------
__global__ void k_final(const float* __restrict__ b3,
                        const float* __restrict__ Wc, const float* __restrict__ bc,
                        float* __restrict__ out, float* __restrict__ hout) {
    int n = blockIdx.x * blockDim.x + threadIdx.x;
    if (n >= N_NODES) return;
    float di = g_dinv[n];
    float2 a = g_c2[n];
    float h0 = tanhf(di * a.x + b3[0]);
    float h1 = tanhf(di * a.y + b3[1]);
    float* o = out + (size_t)n * 10;
#pragma unroll
    for (int j = 0; j < 10; j++)
        o[j] = h0 * Wc[j] + h1 * Wc[10 + j] + bc[j];
    hout[2 * n + 0] = h0;
    hout[2 * n + 1] = h1;
}

// ---------------- launch ----------------
extern "C" void kernel_launch(void* const* d_in, const int* in_sizes, int n_in,
                              void* d_out, int out_size) {
    const float* x  = (const float*)d_in[0];
    const int*   ei = (const int*)d_in[1];        // int32, [2, E] row-major
    const float* W1 = (const float*)d_in[2];
    const float* b1 = (const float*)d_in[3];
    const float* W2 = (const float*)d_in[4];
    const float* b2 = (const float*)d_in[5];
    const float* W3 = (const float*)d_in[6];
    const float* b3 = (const float*)d_in[7];
    const float* Wc = (const float*)d_in[8];
    const float* bc = (const float*)d_in[9];

    const int* src = ei;            // row 0
    const int* dst = ei + N_EDGES;  // row 1

    float* out  = (float*)d_out;                  // [N, 10]
    float* hout = out + (size_t)N_NODES * 10;     // [N, 2]

    const int T = 256;
    const int nodeBlocks = (N_NODES + T - 1) / T;
    const int edgeBlocks = (N_EDGES + T - 1) / T;
    const int mm1Blocks  = (N_NODES + 7) / 8;     // 8 warps/block, warp-per-node

    k_deg_init <<<nodeBlocks, T>>>();
    k_prep     <<<edgeBlocks, T>>>(src, dst);
    k_dinv     <<<nodeBlocks, T>>>();

    k_mm1      <<<mm1Blocks, T>>>(x, W1);
    k_edge4    <<<edgeBlocks, T>>>();

    k_f1mm2    <<<nodeBlocks, T>>>(b1, W2);
    k_edge4    <<<edgeBlocks, T>>>();

    k_f2mm3    <<<nodeBlocks, T>>>(b2, W3);
    k_edge2    <<<edgeBlocks, T>>>();

    k_final    <<<nodeBlocks, T>>>(b3, Wc, bc, out, hout);
}

// round 10
// speedup vs baseline: 2.3906x; 1.0797x over previous
#include <cuda_runtime.h>
#include <cuda_bf16.h>

#define N_NODES 100000
#define N_EDGES 6400000

// ---------------- scratch (allocation-free __device__ globals) ----------------
__device__ int    g_deg [N_NODES];
__device__ float  g_dinv[N_NODES];
__device__ float4 g_f4  [N_NODES];   // pre-scaled per-node features (width 4)
__device__ float4 g_c4  [N_NODES];   // scatter accumulator (width 4)
__device__ float2 g_f2  [N_NODES];   // width-2 (layer 3)
__device__ float2 g_c2  [N_NODES];

// ---------------- vector reductions (validated addresses via clamp) ----------
__device__ __forceinline__ void red_add_v4(float4* addr, float4 v) {
    asm volatile("red.global.add.v4.f32 [%0], {%1,%2,%3,%4};"
                 :: "l"(addr), "f"(v.x), "f"(v.y), "f"(v.z), "f"(v.w) : "memory");
}
__device__ __forceinline__ void red_add_v2(float2* addr, float2 v) {
    asm volatile("red.global.add.v2.f32 [%0], {%1,%2};"
                 :: "l"(addr), "f"(v.x), "f"(v.y) : "memory");
}

__device__ __forceinline__ int clampN(int v) {
    return min(max(v, 0), N_NODES - 1);
}

// ---------------- degree / prep ----------------
__global__ void k_deg_init() {
    int n = blockIdx.x * blockDim.x + threadIdx.x;
    if (n < N_NODES) g_deg[n] = 1;               // self-loop
}

__global__ void k_deg_count(const int* __restrict__ dst) {
    int e = blockIdx.x * blockDim.x + threadIdx.x;
    if (e >= N_EDGES) return;
    atomicAdd(&g_deg[clampN(dst[e])], 1);
}

__global__ void k_dinv() {
    int n = blockIdx.x * blockDim.x + threadIdx.x;
    if (n < N_NODES) g_dinv[n] = rsqrtf((float)g_deg[n]);
}

// ---------------- layer 1: f = (x @ W1) * dinv ; acc = f (self-loop) ----------------
// warp-per-node; conflict-free: k = lane + 32*i -> consecutive lanes read
// consecutive x floats (coalesced) and consecutive sW float4s (no bank conflicts).
__global__ void k_mm1(const float* __restrict__ x, const float* __restrict__ W1) {
    __shared__ float4 sW[128];                   // W1 rows (128x4) as float4
    const float4* W4 = (const float4*)W1;
    for (int i = threadIdx.x; i < 128; i += blockDim.x) sW[i] = W4[i];
    __syncthreads();

    int warp = threadIdx.x >> 5;
    int lane = threadIdx.x & 31;
    int n = blockIdx.x * (blockDim.x >> 5) + warp;
    if (n >= N_NODES) return;

    const float* xr = x + (size_t)n * 128;
    float p0 = 0.f, p1 = 0.f, p2 = 0.f, p3 = 0.f;
#pragma unroll
    for (int i = 0; i < 4; i++) {
        int k = lane + 32 * i;
        float xv = xr[k];
        float4 w = sW[k];
        p0 += xv * w.x; p1 += xv * w.y; p2 += xv * w.z; p3 += xv * w.w;
    }
#pragma unroll
    for (int off = 16; off > 0; off >>= 1) {
        p0 += __shfl_down_sync(0xFFFFFFFFu, p0, off);
        p1 += __shfl_down_sync(0xFFFFFFFFu, p1, off);
        p2 += __shfl_down_sync(0xFFFFFFFFu, p2, off);
        p3 += __shfl_down_sync(0xFFFFFFFFu, p3, off);
    }
    if (lane == 0) {
        float di = g_dinv[n];
        float4 g = make_float4(p0 * di, p1 * di, p2 * di, p3 * di);
        g_f4[n] = g;
        g_c4[n] = g;                             // self-loop contribution
    }
}

// ---------------- edge scatter, width 4: 1 gather sector + 1 RED sector ----------
__global__ void k_edge4(const int* __restrict__ src, const int* __restrict__ dst) {
    int e = blockIdx.x * blockDim.x + threadIdx.x;
    if (e >= N_EDGES) return;
    int s = clampN(src[e]);
    int d = clampN(dst[e]);
    float4 v = g_f4[s];
    red_add_v4(&g_c4[d], v);
}

// ---------------- finalize L1 + matmul L2 (4x4) ----------------
__global__ void k_f1mm2(const float* __restrict__ b1, const float* __restrict__ W2) {
    int n = blockIdx.x * blockDim.x + threadIdx.x;
    if (n >= N_NODES) return;
    float di = g_dinv[n];
    float4 a = g_c4[n];
    float h0 = tanhf(di * a.x + b1[0]);
    float h1 = tanhf(di * a.y + b1[1]);
    float h2 = tanhf(di * a.z + b1[2]);
    float h3 = tanhf(di * a.w + b1[3]);
    float4 g;
    g.x = (h0 * W2[0] + h1 * W2[4] + h2 * W2[8]  + h3 * W2[12]) * di;
    g.y = (h0 * W2[1] + h1 * W2[5] + h2 * W2[9]  + h3 * W2[13]) * di;
    g.z = (h0 * W2[2] + h1 * W2[6] + h2 * W2[10] + h3 * W2[14]) * di;
    g.w = (h0 * W2[3] + h1 * W2[7] + h2 * W2[11] + h3 * W2[15]) * di;
    g_f4[n] = g;
    g_c4[n] = g;                                 // self-loop
}

// ---------------- finalize L2 + matmul L3 (4x2) ----------------
__global__ void k_f2mm3(const float* __restrict__ b2, const float* __restrict__ W3) {
    int n = blockIdx.x * blockDim.x + threadIdx.x;
    if (n >= N_NODES) return;
    float di = g_dinv[n];
    float4 a = g_c4[n];
    float h0 = tanhf(di * a.x + b2[0]);
    float h1 = tanhf(di * a.y + b2[1]);
    float h2 = tanhf(di * a.z + b2[2]);
    float h3 = tanhf(di * a.w + b2[3]);
    float2 g;
    g.x = (h0 * W3[0] + h1 * W3[2] + h2 * W3[4] + h3 * W3[6]) * di;
    g.y = (h0 * W3[1] + h1 * W3[3] + h2 * W3[5] + h3 * W3[7]) * di;
    g_f2[n] = g;
    g_c2[n] = g;                                 // self-loop
}

// ---------------- edge scatter, width 2 ----------------
__global__ void k_edge2(const int* __restrict__ src, const int* __restrict__ dst) {
    int e = blockIdx.x * blockDim.x + threadIdx.x;
    if (e >= N_EDGES) return;
    int s = clampN(src[e]);
    int d = clampN(dst[e]);
    float2 v = g_f2[s];
    red_add_v2(&g_c2[d], v);
}

// ---------------- finalize L3 + classifier ----------------
__global__ void k_final(const float* __restrict__ b3,
                        const float* __restrict__ Wc, const float* __restrict__ bc,
                        float* __restrict__ out, float* __restrict__ hout) {
    int n = blockIdx.x * blockDim.x + threadIdx.x;
    if (n >= N_NODES) return;
    float di = g_dinv[n];
    float2 a = g_c2[n];
    float h0 = tanhf(di * a.x + b3[0]);
    float h1 = tanhf(di * a.y + b3[1]);
    float* o = out + (size_t)n * 10;
#pragma unroll
    for (int j = 0; j < 10; j++)
        o[j] = h0 * Wc[j] + h1 * Wc[10 + j] + bc[j];
    hout[2 * n + 0] = h0;
    hout[2 * n + 1] = h1;
}

// ---------------- launch ----------------
extern "C" void kernel_launch(void* const* d_in, const int* in_sizes, int n_in,
                              void* d_out, int out_size) {
    const float* x  = (const float*)d_in[0];
    const int*   ei = (const int*)d_in[1];        // int32, [2, E] row-major
    const float* W1 = (const float*)d_in[2];
    const float* b1 = (const float*)d_in[3];
    const float* W2 = (const float*)d_in[4];
    const float* b2 = (const float*)d_in[5];
    const float* W3 = (const float*)d_in[6];
    const float* b3 = (const float*)d_in[7];
    const float* Wc = (const float*)d_in[8];
    const float* bc = (const float*)d_in[9];

    const int* src = ei;            // row 0
    const int* dst = ei + N_EDGES;  // row 1

    float* out  = (float*)d_out;                  // [N, 10]
    float* hout = out + (size_t)N_NODES * 10;     // [N, 2]

    const int T = 256;
    const int nodeBlocks = (N_NODES + T - 1) / T;
    const int edgeBlocks = (N_EDGES + T - 1) / T;
    const int mm1Blocks  = (N_NODES + 7) / 8;     // 8 warps/block, warp-per-node

    k_deg_init <<<nodeBlocks, T>>>();
    k_deg_count<<<edgeBlocks, T>>>(dst);
    k_dinv     <<<nodeBlocks, T>>>();

    k_mm1      <<<mm1Blocks, T>>>(x, W1);
    k_edge4    <<<edgeBlocks, T>>>(src, dst);

    k_f1mm2    <<<nodeBlocks, T>>>(b1, W2);
    k_edge4    <<<edgeBlocks, T>>>(src, dst);

    k_f2mm3    <<<nodeBlocks, T>>>(b2, W3);
    k_edge2    <<<edgeBlocks, T>>>(src, dst);

    k_final    <<<nodeBlocks, T>>>(b3, Wc, bc, out, hout);
}